// round 10
// baseline (speedup 1.0000x reference)
#include <cuda_runtime.h>
#include <cuda_bf16.h>
#include <cstdint>

#define N_NODES 100000
#define N_GRAPHS 2000
#define CAP 128            // per-node bucket capacity (deg ~ Poisson(32), max ~66)
#define F1 64
#define F2 128
#define BN_EPS 1e-5f

// ------------------------- device scratch (no allocs allowed) ---------------
__device__ int   g_cnti[N_NODES];
__device__ int   g_bucket[(size_t)N_NODES * CAP];
__device__ float g_dinv[N_NODES];
__device__ __align__(16) float g_xs[(size_t)N_NODES * 16];    // x * dinv, padded 10->16
__device__ __align__(16) float g_aggx[(size_t)N_NODES * 16];  // aggregated xs
__device__ __align__(16) float g_out1[(size_t)N_NODES * F1];  // conv1 output (pre-BN)
__device__ __align__(16) float g_a1s[(size_t)N_NODES * F1];   // relu(bn(conv1)) * dinv
__device__ __align__(16) float g_agg1[(size_t)N_NODES * F1];  // aggregated a1s
__device__ __align__(16) float g_out2[(size_t)N_NODES * F2];  // conv2 output (pre-BN)
__device__ float g_sum1[F1], g_sq1[F1];
__device__ float g_sum2[F2], g_sq2[F2];
__device__ float g_pool[N_GRAPHS * F2];
__device__ float g_cnt[N_GRAPHS];

#define FMA_F32X2(d, a, b, c) \
    asm("fma.rn.f32x2 %0, %1, %2, %3;" : "=l"(d) : "l"(a), "l"(b), "l"(c))
#define ADD_F32X2(d, a, b) \
    asm("add.rn.f32x2 %0, %1, %2;" : "=l"(d) : "l"(a), "l"(b))

__device__ __forceinline__ float2 unpack2(unsigned long long p) {
    unsigned int lo, hi;
    asm("mov.b64 {%0, %1}, %2;" : "=r"(lo), "=r"(hi) : "l"(p));
    return make_float2(__uint_as_float(lo), __uint_as_float(hi));
}

// ------------------------- kernels ------------------------------------------

__global__ void k_zero() {
    int i = blockIdx.x * blockDim.x + threadIdx.x;
    int stride = gridDim.x * blockDim.x;
    for (int j = i; j < N_NODES; j += stride) g_cnti[j] = 0;
    for (int j = i; j < N_GRAPHS * F2; j += stride) g_pool[j] = 0.f;
    for (int j = i; j < N_GRAPHS; j += stride) g_cnt[j] = 0.f;
    if (i < F1) { g_sum1[i] = 0.f; g_sq1[i] = 0.f; }
    if (i < F2) { g_sum2[i] = 0.f; g_sq2[i] = 0.f; }
}

// Direct bucket fill.
__global__ void k_fill(const int* __restrict__ src, const int* __restrict__ dst, int E) {
    int i = blockIdx.x * blockDim.x + threadIdx.x;
    if (i >= E) return;
    int d = dst[i];
    int p = atomicAdd(&g_cnti[d], 1);
    if (p < CAP) g_bucket[(size_t)d * CAP + p] = src[i];
}

// dinv + xs = x*dinv (padded to 16 floats).
__global__ void k_prep(const float* __restrict__ x) {
    int r = blockIdx.x * blockDim.x + threadIdx.x;
    if (r >= N_NODES) return;
    float di = rsqrtf((float)g_cnti[r] + 1.0f);
    g_dinv[r] = di;
    const float* xr = x + (size_t)r * 10;
    float4* o = (float4*)(g_xs + (size_t)r * 16);
    o[0] = make_float4(xr[0] * di, xr[1] * di, xr[2] * di, xr[3] * di);
    o[1] = make_float4(xr[4] * di, xr[5] * di, xr[6] * di, xr[7] * di);
    o[2] = make_float4(xr[8] * di, xr[9] * di, 0.f, 0.f);
    o[3] = make_float4(0.f, 0.f, 0.f, 0.f);
}

// Aggregate xs (16 floats/row). 4 lanes x 16B per row (8 rows/warp), packed adds.
__global__ void __launch_bounds__(256) k_aggx() {
    int tid = threadIdx.x;
    int ql = tid & 3;
    unsigned qmask = 0xFu << ((tid & 31) & ~3);
    int gq = (blockIdx.x * blockDim.x + tid) >> 2;
    int nq = (gridDim.x * blockDim.x) >> 2;
    const ulonglong2* xs2 = (const ulonglong2*)g_xs;   // 4 x 16B per row
    float4* ag4 = (float4*)g_aggx;
    for (int row = gq; row < N_NODES; row += nq) {
        int deg = min(g_cnti[row], CAP);
        const int* bkt = g_bucket + (size_t)row * CAP;
        ulonglong2 acc = xs2[(size_t)row * 4 + ql];
        int e = 0;
        for (; e + 4 <= deg; e += 4) {
            int myidx = bkt[e + ql];
            int s0 = __shfl_sync(qmask, myidx, 0, 4);
            int s1 = __shfl_sync(qmask, myidx, 1, 4);
            int s2 = __shfl_sync(qmask, myidx, 2, 4);
            int s3 = __shfl_sync(qmask, myidx, 3, 4);
            ulonglong2 v0 = xs2[(size_t)s0 * 4 + ql];
            ulonglong2 v1 = xs2[(size_t)s1 * 4 + ql];
            ulonglong2 v2 = xs2[(size_t)s2 * 4 + ql];
            ulonglong2 v3 = xs2[(size_t)s3 * 4 + ql];
            ADD_F32X2(acc.x, acc.x, v0.x); ADD_F32X2(acc.y, acc.y, v0.y);
            ADD_F32X2(acc.x, acc.x, v1.x); ADD_F32X2(acc.y, acc.y, v1.y);
            ADD_F32X2(acc.x, acc.x, v2.x); ADD_F32X2(acc.y, acc.y, v2.y);
            ADD_F32X2(acc.x, acc.x, v3.x); ADD_F32X2(acc.y, acc.y, v3.y);
        }
        if (e < deg) {
            int n = deg - e;
            int myidx = (ql < n) ? bkt[e + ql] : 0;
            for (int j = 0; j < n; j++) {
                int s = __shfl_sync(qmask, myidx, j, 4);
                ulonglong2 v = xs2[(size_t)s * 4 + ql];
                ADD_F32X2(acc.x, acc.x, v.x);
                ADD_F32X2(acc.y, acc.y, v.y);
            }
        }
        float di = g_dinv[row];
        float2 lo = unpack2(acc.x), hi = unpack2(acc.y);
        ag4[(size_t)row * 4 + ql] =
            make_float4(lo.x * di, lo.y * di, hi.x * di, hi.y * di);
    }
}

// out1 = aggx[:, :10] @ W1, fused BN1 stats. Block: 64 (features) x 4 (rows).
__global__ void __launch_bounds__(256) k_gemm1b(const float* __restrict__ W1) {
    __shared__ float Ws[10 * F1];
    __shared__ float xs[4][16];
    __shared__ float s_sum[F1], s_sq[F1];
    int tx = threadIdx.x;  // 0..63 feature
    int ty = threadIdx.y;  // 0..3 row
    int t = ty * 64 + tx;
    for (int j = t; j < 10 * F1; j += 256) Ws[j] = W1[j];
    if (t < F1) { s_sum[t] = 0.f; s_sq[t] = 0.f; }
    __syncthreads();
    float lsum = 0.f, lsq = 0.f;
    for (int rb = blockIdx.x * 4; rb < N_NODES; rb += gridDim.x * 4) {
        if (t < 64) {
            int rr = rb + (t >> 4);
            xs[t >> 4][t & 15] = (rr < N_NODES) ? g_aggx[(size_t)rr * 16 + (t & 15)] : 0.f;
        }
        __syncthreads();
        int row = rb + ty;
        if (row < N_NODES) {
            float acc = 0.f;
#pragma unroll
            for (int k = 0; k < 10; k++) acc += xs[ty][k] * Ws[k * F1 + tx];
            g_out1[(size_t)row * F1 + tx] = acc;
            lsum += acc;
            lsq += acc * acc;
        }
        __syncthreads();
    }
    atomicAdd(&s_sum[tx], lsum);
    atomicAdd(&s_sq[tx], lsq);
    __syncthreads();
    if (t < F1) {
        atomicAdd(&g_sum1[t], s_sum[t]);
        atomicAdd(&g_sq1[t], s_sq[t]);
    }
}

// a1s = relu(bn1(out1)) * dinv. Elementwise, float4-vectorized.
__global__ void __launch_bounds__(256) k_mid(const float* __restrict__ gam,
                                             const float* __restrict__ bet) {
    __shared__ float sc[F1], sh[F1];
    int tid = threadIdx.x;
    if (tid < F1) {
        float mu = g_sum1[tid] * (1.0f / N_NODES);
        float var = g_sq1[tid] * (1.0f / N_NODES) - mu * mu;
        float s = gam[tid] * rsqrtf(var + BN_EPS);
        sc[tid] = s;
        sh[tid] = bet[tid] - mu * s;
    }
    __syncthreads();
    const float4* in = (const float4*)g_out1;
    float4* outp = (float4*)g_a1s;
    int total = N_NODES * F1 / 4;
    for (int i = blockIdx.x * blockDim.x + tid; i < total; i += gridDim.x * blockDim.x) {
        int row = i >> 4;           // 16 float4 per row
        int f = (i & 15) * 4;
        float di = g_dinv[row];
        float4 v = in[i];
        float4 o;
        o.x = fmaxf(v.x * sc[f + 0] + sh[f + 0], 0.f) * di;
        o.y = fmaxf(v.y * sc[f + 1] + sh[f + 1], 0.f) * di;
        o.z = fmaxf(v.z * sc[f + 2] + sh[f + 2], 0.f) * di;
        o.w = fmaxf(v.w * sc[f + 3] + sh[f + 3], 0.f) * di;
        outp[i] = o;
    }
}

// Aggregate a1s (64 floats/row). 16 lanes x 16B per row (2 rows/warp), packed adds.
// agg1[d] = dinv[d] * (a1s[d] + sum_s a1s[s]).
__global__ void __launch_bounds__(256) k_agg1() {
    int tid = threadIdx.x;
    int hl = tid & 15;
    unsigned hmask = 0xFFFFu << ((tid & 31) & 16);
    int gh = (blockIdx.x * blockDim.x + tid) >> 4;
    int nh = (gridDim.x * blockDim.x) >> 4;
    const ulonglong2* a2 = (const ulonglong2*)g_a1s;   // 16 x 16B per row
    float4* o4 = (float4*)g_agg1;
    for (int row = gh; row < N_NODES; row += nh) {
        int deg = min(g_cnti[row], CAP);
        const int* bkt = g_bucket + (size_t)row * CAP;
        ulonglong2 acc = a2[(size_t)row * 16 + hl];
        int e = 0;
        while (e < deg) {
            int n = min(16, deg - e);
            int myidx = (hl < n) ? bkt[e + hl] : 0;
            e += n;
            int j = 0;
            for (; j + 4 <= n; j += 4) {
                int s0 = __shfl_sync(hmask, myidx, j, 16);
                int s1 = __shfl_sync(hmask, myidx, j + 1, 16);
                int s2 = __shfl_sync(hmask, myidx, j + 2, 16);
                int s3 = __shfl_sync(hmask, myidx, j + 3, 16);
                ulonglong2 v0 = a2[(size_t)s0 * 16 + hl];
                ulonglong2 v1 = a2[(size_t)s1 * 16 + hl];
                ulonglong2 v2 = a2[(size_t)s2 * 16 + hl];
                ulonglong2 v3 = a2[(size_t)s3 * 16 + hl];
                ADD_F32X2(acc.x, acc.x, v0.x); ADD_F32X2(acc.y, acc.y, v0.y);
                ADD_F32X2(acc.x, acc.x, v1.x); ADD_F32X2(acc.y, acc.y, v1.y);
                ADD_F32X2(acc.x, acc.x, v2.x); ADD_F32X2(acc.y, acc.y, v2.y);
                ADD_F32X2(acc.x, acc.x, v3.x); ADD_F32X2(acc.y, acc.y, v3.y);
            }
            for (; j < n; j++) {
                int s = __shfl_sync(hmask, myidx, j, 16);
                ulonglong2 v = a2[(size_t)s * 16 + hl];
                ADD_F32X2(acc.x, acc.x, v.x);
                ADD_F32X2(acc.y, acc.y, v.y);
            }
        }
        float di = g_dinv[row];
        float2 lo = unpack2(acc.x), hi = unpack2(acc.y);
        o4[(size_t)row * 16 + hl] =
            make_float4(lo.x * di, lo.y * di, hi.x * di, hi.y * di);
    }
}

// out2 = agg1 @ W2 via packed f32x2 (2 rows at once), fused BN2 stats.
__global__ void __launch_bounds__(128) k_gemm2b(const float* __restrict__ W2) {
    int tx = threadIdx.x;
    float w2[F1];
#pragma unroll
    for (int k = 0; k < F1; k++) w2[k] = W2[(size_t)k * F2 + tx];

    __shared__ float2 a_s[F1];   // .x = row r, .y = row r+1
    float lsum = 0.f, lsq = 0.f;

    for (int r = blockIdx.x * 2; r < N_NODES; r += gridDim.x * 2) {
        int lr = tx >> 6;
        int kk = tx & 63;
        int rr = r + lr;
        float av = (rr < N_NODES) ? g_agg1[(size_t)rr * F1 + kk] : 0.f;
        __syncthreads();
        if (lr == 0) a_s[kk].x = av; else a_s[kk].y = av;
        __syncthreads();

        unsigned long long accp = 0ULL;  // packed (0.f, 0.f)
        const unsigned long long* ap = (const unsigned long long*)a_s;
#pragma unroll
        for (int k = 0; k < F1; k++) {
            unsigned long long wp;
            asm("mov.b64 %0, {%1, %1};" : "=l"(wp) : "r"(__float_as_uint(w2[k])));
            FMA_F32X2(accp, ap[k], wp, accp);
        }
        float2 a01 = unpack2(accp);
        float acc0 = a01.x, acc1 = a01.y;

        g_out2[(size_t)r * F2 + tx] = acc0;
        lsum += acc0; lsq += acc0 * acc0;
        if (r + 1 < N_NODES) {
            g_out2[(size_t)(r + 1) * F2 + tx] = acc1;
            lsum += acc1; lsq += acc1 * acc1;
        }
    }
    atomicAdd(&g_sum2[tx], lsum);
    atomicAdd(&g_sq2[tx], lsq);
}

// Pooling: relu(bn2(out2)) segment-summed by sorted batch id. BN inline.
__global__ void k_pool(const int* __restrict__ batch,
                       const float* __restrict__ gam,
                       const float* __restrict__ bet) {
    int tx = threadIdx.x;  // 0..127
    float mu = g_sum2[tx] * (1.0f / N_NODES);
    float var = g_sq2[tx] * (1.0f / N_NODES) - mu * mu;
    float sc = gam[tx] * rsqrtf(var + BN_EPS);
    float sh = bet[tx] - mu * sc;

    int rpb = (N_NODES + gridDim.x - 1) / gridDim.x;
    int r0 = blockIdx.x * rpb;
    int r1 = min(r0 + rpb, N_NODES);
    if (r0 >= r1) return;
    int curb = batch[r0];
    float acc = 0.f, c = 0.f;
    for (int r = r0; r < r1; r++) {
        int b = batch[r];
        if (b != curb) {
            atomicAdd(&g_pool[curb * F2 + tx], acc);
            if (tx == 0) atomicAdd(&g_cnt[curb], c);
            acc = 0.f; c = 0.f;
            curb = b;
        }
        float v = g_out2[(size_t)r * F2 + tx];
        acc += fmaxf(v * sc + sh, 0.f);
        c += 1.f;
    }
    atomicAdd(&g_pool[curb * F2 + tx], acc);
    if (tx == 0) atomicAdd(&g_cnt[curb], c);
}

// Final MLP head. One block (64 threads) per graph.
__global__ void k_mlp(const float* __restrict__ fW1, const float* __restrict__ fb1,
                      const float* __restrict__ fW2, const float* __restrict__ fb2,
                      float* __restrict__ out) {
    int g = blockIdx.x;
    int tx = threadIdx.x;  // 0..63
    __shared__ float prow[F2];
    __shared__ float partial[2];
    float c = fmaxf(g_cnt[g], 1.0f);
    float inv = 1.0f / c;
    prow[tx] = g_pool[g * F2 + tx] * inv;
    prow[tx + 64] = g_pool[g * F2 + tx + 64] * inv;
    __syncthreads();
    float h = fb1[tx];
#pragma unroll 8
    for (int k = 0; k < F2; k++) h += prow[k] * fW1[(size_t)k * 64 + tx];
    h = fmaxf(h, 0.f);
    float p = h * fW2[tx];
#pragma unroll
    for (int off = 16; off; off >>= 1) p += __shfl_down_sync(0xffffffff, p, off);
    if ((tx & 31) == 0) partial[tx >> 5] = p;
    __syncthreads();
    if (tx == 0) out[g] = partial[0] + partial[1] + fb2[0];
}

// ------------------------- launch --------------------------------------------
extern "C" void kernel_launch(void* const* d_in, const int* in_sizes, int n_in,
                              void* d_out, int out_size) {
    const float* x   = (const float*)d_in[0];
    const int*   src = (const int*)d_in[1];
    const int*   dst = (const int*)d_in[2];
    const int*   bat = (const int*)d_in[3];
    const float* W1  = (const float*)d_in[4];
    // d_in[5] = b1 (cancels in BN)
    const float* g1  = (const float*)d_in[6];
    const float* be1 = (const float*)d_in[7];
    const float* W2  = (const float*)d_in[8];
    // d_in[9] = b2 (cancels in BN)
    const float* g2  = (const float*)d_in[10];
    const float* be2 = (const float*)d_in[11];
    const float* fW1 = (const float*)d_in[12];
    const float* fb1 = (const float*)d_in[13];
    const float* fW2 = (const float*)d_in[14];
    const float* fb2 = (const float*)d_in[15];
    float* out = (float*)d_out;

    int E = in_sizes[1];

    k_zero<<<512, 256>>>();
    k_fill<<<(E + 255) / 256, 256>>>(src, dst, E);
    k_prep<<<(N_NODES + 255) / 256, 256>>>(x);

    k_aggx<<<2048, 256>>>();
    k_gemm1b<<<2048, dim3(64, 4)>>>(W1);
    k_mid<<<2048, 256>>>(g1, be1);

    k_agg1<<<2048, 256>>>();
    k_gemm2b<<<2048, 128>>>(W2);

    k_pool<<<1024, 128>>>(bat, g2, be2);
    k_mlp<<<N_GRAPHS, 64>>>(fW1, fb1, fW2, fb2, out);
}

// round 11
// speedup vs baseline: 1.3264x; 1.3264x over previous
#include <cuda_runtime.h>
#include <cuda_bf16.h>
#include <cstdint>

#define N_NODES 100000
#define N_GRAPHS 2000
#define CAP 128            // per-node bucket capacity (deg ~ Poisson(32), max ~66)
#define F1 64
#define F2 128
#define BN_EPS 1e-5f

// ------------------------- device scratch (no allocs allowed) ---------------
__device__ int   g_cnti[N_NODES];
__device__ int   g_bucket[(size_t)N_NODES * CAP];
__device__ float g_dinv[N_NODES];
__device__ __align__(16) float g_xs[(size_t)N_NODES * 16];    // x * dinv, padded 10->16
__device__ __align__(16) float g_aggx[(size_t)N_NODES * 16];  // aggregated xs
__device__ __align__(16) float g_out1[(size_t)N_NODES * F1];  // conv1 output (pre-BN)
__device__ __align__(16) float g_a1s[(size_t)N_NODES * F1];   // relu(bn(conv1)) * dinv
__device__ __align__(16) float g_agg1[(size_t)N_NODES * F1];  // aggregated a1s
__device__ __align__(16) float g_out2[(size_t)N_NODES * F2];  // conv2 output (pre-BN)
__device__ float g_sum1[F1], g_sq1[F1];
__device__ float g_sum2[F2], g_sq2[F2];
__device__ float g_pool[N_GRAPHS * F2];
__device__ float g_cnt[N_GRAPHS];

#define FMA_F32X2(d, a, b, c) \
    asm("fma.rn.f32x2 %0, %1, %2, %3;" : "=l"(d) : "l"(a), "l"(b), "l"(c))
#define ADD_F32X2(d, a, b) \
    asm("add.rn.f32x2 %0, %1, %2;" : "=l"(d) : "l"(a), "l"(b))

__device__ __forceinline__ float2 unpack2(unsigned long long p) {
    unsigned int lo, hi;
    asm("mov.b64 {%0, %1}, %2;" : "=r"(lo), "=r"(hi) : "l"(p));
    return make_float2(__uint_as_float(lo), __uint_as_float(hi));
}

// ------------------------- kernels ------------------------------------------

__global__ void k_zero() {
    int i = blockIdx.x * blockDim.x + threadIdx.x;
    int stride = gridDim.x * blockDim.x;
    for (int j = i; j < N_NODES; j += stride) g_cnti[j] = 0;
    for (int j = i; j < N_GRAPHS * F2; j += stride) g_pool[j] = 0.f;
    for (int j = i; j < N_GRAPHS; j += stride) g_cnt[j] = 0.f;
    if (i < F1) { g_sum1[i] = 0.f; g_sq1[i] = 0.f; }
    if (i < F2) { g_sum2[i] = 0.f; g_sq2[i] = 0.f; }
}

// Direct bucket fill.
__global__ void k_fill(const int* __restrict__ src, const int* __restrict__ dst, int E) {
    int i = blockIdx.x * blockDim.x + threadIdx.x;
    if (i >= E) return;
    int d = dst[i];
    int p = atomicAdd(&g_cnti[d], 1);
    if (p < CAP) g_bucket[(size_t)d * CAP + p] = src[i];
}

// dinv + xs = x*dinv (padded to 16 floats).
__global__ void k_prep(const float* __restrict__ x) {
    int r = blockIdx.x * blockDim.x + threadIdx.x;
    if (r >= N_NODES) return;
    float di = rsqrtf((float)g_cnti[r] + 1.0f);
    g_dinv[r] = di;
    const float* xr = x + (size_t)r * 10;
    float4* o = (float4*)(g_xs + (size_t)r * 16);
    o[0] = make_float4(xr[0] * di, xr[1] * di, xr[2] * di, xr[3] * di);
    o[1] = make_float4(xr[4] * di, xr[5] * di, xr[6] * di, xr[7] * di);
    o[2] = make_float4(xr[8] * di, xr[9] * di, 0.f, 0.f);
    o[3] = make_float4(0.f, 0.f, 0.f, 0.f);
}

// Aggregate xs (16 floats/row). 4 lanes x 16B per row (8 rows/warp), packed adds.
__global__ void __launch_bounds__(256) k_aggx() {
    int tid = threadIdx.x;
    int ql = tid & 3;
    unsigned qmask = 0xFu << ((tid & 31) & ~3);
    int gq = (blockIdx.x * blockDim.x + tid) >> 2;
    int nq = (gridDim.x * blockDim.x) >> 2;
    const ulonglong2* xs2 = (const ulonglong2*)g_xs;   // 4 x 16B per row
    float4* ag4 = (float4*)g_aggx;
    for (int row = gq; row < N_NODES; row += nq) {
        int deg = min(g_cnti[row], CAP);
        const int* bkt = g_bucket + (size_t)row * CAP;
        ulonglong2 acc = xs2[(size_t)row * 4 + ql];
        int e = 0;
        for (; e + 4 <= deg; e += 4) {
            int myidx = bkt[e + ql];
            int s0 = __shfl_sync(qmask, myidx, 0, 4);
            int s1 = __shfl_sync(qmask, myidx, 1, 4);
            int s2 = __shfl_sync(qmask, myidx, 2, 4);
            int s3 = __shfl_sync(qmask, myidx, 3, 4);
            ulonglong2 v0 = xs2[(size_t)s0 * 4 + ql];
            ulonglong2 v1 = xs2[(size_t)s1 * 4 + ql];
            ulonglong2 v2 = xs2[(size_t)s2 * 4 + ql];
            ulonglong2 v3 = xs2[(size_t)s3 * 4 + ql];
            ADD_F32X2(acc.x, acc.x, v0.x); ADD_F32X2(acc.y, acc.y, v0.y);
            ADD_F32X2(acc.x, acc.x, v1.x); ADD_F32X2(acc.y, acc.y, v1.y);
            ADD_F32X2(acc.x, acc.x, v2.x); ADD_F32X2(acc.y, acc.y, v2.y);
            ADD_F32X2(acc.x, acc.x, v3.x); ADD_F32X2(acc.y, acc.y, v3.y);
        }
        if (e < deg) {
            int n = deg - e;
            int myidx = (ql < n) ? bkt[e + ql] : 0;
            for (int j = 0; j < n; j++) {
                int s = __shfl_sync(qmask, myidx, j, 4);
                ulonglong2 v = xs2[(size_t)s * 4 + ql];
                ADD_F32X2(acc.x, acc.x, v.x);
                ADD_F32X2(acc.y, acc.y, v.y);
            }
        }
        float di = g_dinv[row];
        float2 lo = unpack2(acc.x), hi = unpack2(acc.y);
        ag4[(size_t)row * 4 + ql] =
            make_float4(lo.x * di, lo.y * di, hi.x * di, hi.y * di);
    }
}

// out1 = aggx[:, :10] @ W1, fused BN1 stats. Block: 64 (features) x 4 (rows).
__global__ void __launch_bounds__(256) k_gemm1b(const float* __restrict__ W1) {
    __shared__ float Ws[10 * F1];
    __shared__ float xs[4][16];
    __shared__ float s_sum[F1], s_sq[F1];
    int tx = threadIdx.x;  // 0..63 feature
    int ty = threadIdx.y;  // 0..3 row
    int t = ty * 64 + tx;
    for (int j = t; j < 10 * F1; j += 256) Ws[j] = W1[j];
    if (t < F1) { s_sum[t] = 0.f; s_sq[t] = 0.f; }
    __syncthreads();
    float lsum = 0.f, lsq = 0.f;
    for (int rb = blockIdx.x * 4; rb < N_NODES; rb += gridDim.x * 4) {
        if (t < 64) {
            int rr = rb + (t >> 4);
            xs[t >> 4][t & 15] = (rr < N_NODES) ? g_aggx[(size_t)rr * 16 + (t & 15)] : 0.f;
        }
        __syncthreads();
        int row = rb + ty;
        if (row < N_NODES) {
            float acc = 0.f;
#pragma unroll
            for (int k = 0; k < 10; k++) acc += xs[ty][k] * Ws[k * F1 + tx];
            g_out1[(size_t)row * F1 + tx] = acc;
            lsum += acc;
            lsq += acc * acc;
        }
        __syncthreads();
    }
    atomicAdd(&s_sum[tx], lsum);
    atomicAdd(&s_sq[tx], lsq);
    __syncthreads();
    if (t < F1) {
        atomicAdd(&g_sum1[t], s_sum[t]);
        atomicAdd(&g_sq1[t], s_sq[t]);
    }
}

// a1s = relu(bn1(out1)) * dinv. Elementwise, float4-vectorized.
__global__ void __launch_bounds__(256) k_mid(const float* __restrict__ gam,
                                             const float* __restrict__ bet) {
    __shared__ float sc[F1], sh[F1];
    int tid = threadIdx.x;
    if (tid < F1) {
        float mu = g_sum1[tid] * (1.0f / N_NODES);
        float var = g_sq1[tid] * (1.0f / N_NODES) - mu * mu;
        float s = gam[tid] * rsqrtf(var + BN_EPS);
        sc[tid] = s;
        sh[tid] = bet[tid] - mu * s;
    }
    __syncthreads();
    const float4* in = (const float4*)g_out1;
    float4* outp = (float4*)g_a1s;
    int total = N_NODES * F1 / 4;
    for (int i = blockIdx.x * blockDim.x + tid; i < total; i += gridDim.x * blockDim.x) {
        int row = i >> 4;           // 16 float4 per row
        int f = (i & 15) * 4;
        float di = g_dinv[row];
        float4 v = in[i];
        float4 o;
        o.x = fmaxf(v.x * sc[f + 0] + sh[f + 0], 0.f) * di;
        o.y = fmaxf(v.y * sc[f + 1] + sh[f + 1], 0.f) * di;
        o.z = fmaxf(v.z * sc[f + 2] + sh[f + 2], 0.f) * di;
        o.w = fmaxf(v.w * sc[f + 3] + sh[f + 3], 0.f) * di;
        outp[i] = o;
    }
}

// Aggregate a1s (64 floats/row). 16 lanes x 16B per row (2 rows/warp), packed adds.
// agg1[d] = dinv[d] * (a1s[d] + sum_s a1s[s]).
__global__ void __launch_bounds__(256) k_agg1() {
    int tid = threadIdx.x;
    int hl = tid & 15;
    unsigned hmask = 0xFFFFu << ((tid & 31) & 16);
    int gh = (blockIdx.x * blockDim.x + tid) >> 4;
    int nh = (gridDim.x * blockDim.x) >> 4;
    const ulonglong2* a2 = (const ulonglong2*)g_a1s;   // 16 x 16B per row
    float4* o4 = (float4*)g_agg1;
    for (int row = gh; row < N_NODES; row += nh) {
        int deg = min(g_cnti[row], CAP);
        const int* bkt = g_bucket + (size_t)row * CAP;
        ulonglong2 acc = a2[(size_t)row * 16 + hl];
        int e = 0;
        while (e < deg) {
            int n = min(16, deg - e);
            int myidx = (hl < n) ? bkt[e + hl] : 0;
            e += n;
            int j = 0;
            for (; j + 4 <= n; j += 4) {
                int s0 = __shfl_sync(hmask, myidx, j, 16);
                int s1 = __shfl_sync(hmask, myidx, j + 1, 16);
                int s2 = __shfl_sync(hmask, myidx, j + 2, 16);
                int s3 = __shfl_sync(hmask, myidx, j + 3, 16);
                ulonglong2 v0 = a2[(size_t)s0 * 16 + hl];
                ulonglong2 v1 = a2[(size_t)s1 * 16 + hl];
                ulonglong2 v2 = a2[(size_t)s2 * 16 + hl];
                ulonglong2 v3 = a2[(size_t)s3 * 16 + hl];
                ADD_F32X2(acc.x, acc.x, v0.x); ADD_F32X2(acc.y, acc.y, v0.y);
                ADD_F32X2(acc.x, acc.x, v1.x); ADD_F32X2(acc.y, acc.y, v1.y);
                ADD_F32X2(acc.x, acc.x, v2.x); ADD_F32X2(acc.y, acc.y, v2.y);
                ADD_F32X2(acc.x, acc.x, v3.x); ADD_F32X2(acc.y, acc.y, v3.y);
            }
            for (; j < n; j++) {
                int s = __shfl_sync(hmask, myidx, j, 16);
                ulonglong2 v = a2[(size_t)s * 16 + hl];
                ADD_F32X2(acc.x, acc.x, v.x);
                ADD_F32X2(acc.y, acc.y, v.y);
            }
        }
        float di = g_dinv[row];
        float2 lo = unpack2(acc.x), hi = unpack2(acc.y);
        o4[(size_t)row * 16 + hl] =
            make_float4(lo.x * di, lo.y * di, hi.x * di, hi.y * di);
    }
}

// out2 = agg1 @ W2 via packed f32x2 (2 rows at once), fused BN2 stats.
__global__ void __launch_bounds__(128) k_gemm2b(const float* __restrict__ W2) {
    int tx = threadIdx.x;
    float w2[F1];
#pragma unroll
    for (int k = 0; k < F1; k++) w2[k] = W2[(size_t)k * F2 + tx];

    __shared__ float2 a_s[F1];   // .x = row r, .y = row r+1
    float lsum = 0.f, lsq = 0.f;

    for (int r = blockIdx.x * 2; r < N_NODES; r += gridDim.x * 2) {
        int lr = tx >> 6;
        int kk = tx & 63;
        int rr = r + lr;
        float av = (rr < N_NODES) ? g_agg1[(size_t)rr * F1 + kk] : 0.f;
        __syncthreads();
        if (lr == 0) a_s[kk].x = av; else a_s[kk].y = av;
        __syncthreads();

        unsigned long long accp = 0ULL;  // packed (0.f, 0.f)
        const unsigned long long* ap = (const unsigned long long*)a_s;
#pragma unroll
        for (int k = 0; k < F1; k++) {
            unsigned long long wp;
            asm("mov.b64 %0, {%1, %1};" : "=l"(wp) : "r"(__float_as_uint(w2[k])));
            FMA_F32X2(accp, ap[k], wp, accp);
        }
        float2 a01 = unpack2(accp);
        float acc0 = a01.x, acc1 = a01.y;

        g_out2[(size_t)r * F2 + tx] = acc0;
        lsum += acc0; lsq += acc0 * acc0;
        if (r + 1 < N_NODES) {
            g_out2[(size_t)(r + 1) * F2 + tx] = acc1;
            lsum += acc1; lsq += acc1 * acc1;
        }
    }
    atomicAdd(&g_sum2[tx], lsum);
    atomicAdd(&g_sq2[tx], lsq);
}

// Pooling: relu(bn2(out2)) segment-summed by sorted batch id. BN inline.
__global__ void k_pool(const int* __restrict__ batch,
                       const float* __restrict__ gam,
                       const float* __restrict__ bet) {
    int tx = threadIdx.x;  // 0..127
    float mu = g_sum2[tx] * (1.0f / N_NODES);
    float var = g_sq2[tx] * (1.0f / N_NODES) - mu * mu;
    float sc = gam[tx] * rsqrtf(var + BN_EPS);
    float sh = bet[tx] - mu * sc;

    int rpb = (N_NODES + gridDim.x - 1) / gridDim.x;
    int r0 = blockIdx.x * rpb;
    int r1 = min(r0 + rpb, N_NODES);
    if (r0 >= r1) return;
    int curb = batch[r0];
    float acc = 0.f, c = 0.f;
    for (int r = r0; r < r1; r++) {
        int b = batch[r];
        if (b != curb) {
            atomicAdd(&g_pool[curb * F2 + tx], acc);
            if (tx == 0) atomicAdd(&g_cnt[curb], c);
            acc = 0.f; c = 0.f;
            curb = b;
        }
        float v = g_out2[(size_t)r * F2 + tx];
        acc += fmaxf(v * sc + sh, 0.f);
        c += 1.f;
    }
    atomicAdd(&g_pool[curb * F2 + tx], acc);
    if (tx == 0) atomicAdd(&g_cnt[curb], c);
}

// Final MLP head. One block (64 threads) per graph.
__global__ void k_mlp(const float* __restrict__ fW1, const float* __restrict__ fb1,
                      const float* __restrict__ fW2, const float* __restrict__ fb2,
                      float* __restrict__ out) {
    int g = blockIdx.x;
    int tx = threadIdx.x;  // 0..63
    __shared__ float prow[F2];
    __shared__ float partial[2];
    float c = fmaxf(g_cnt[g], 1.0f);
    float inv = 1.0f / c;
    prow[tx] = g_pool[g * F2 + tx] * inv;
    prow[tx + 64] = g_pool[g * F2 + tx + 64] * inv;
    __syncthreads();
    float h = fb1[tx];
#pragma unroll 8
    for (int k = 0; k < F2; k++) h += prow[k] * fW1[(size_t)k * 64 + tx];
    h = fmaxf(h, 0.f);
    float p = h * fW2[tx];
#pragma unroll
    for (int off = 16; off; off >>= 1) p += __shfl_down_sync(0xffffffff, p, off);
    if ((tx & 31) == 0) partial[tx >> 5] = p;
    __syncthreads();
    if (tx == 0) out[g] = partial[0] + partial[1] + fb2[0];
}

// ------------------------- launch --------------------------------------------
extern "C" void kernel_launch(void* const* d_in, const int* in_sizes, int n_in,
                              void* d_out, int out_size) {
    const float* x   = (const float*)d_in[0];
    const int*   src = (const int*)d_in[1];
    const int*   dst = (const int*)d_in[2];
    const int*   bat = (const int*)d_in[3];
    const float* W1  = (const float*)d_in[4];
    // d_in[5] = b1 (cancels in BN)
    const float* g1  = (const float*)d_in[6];
    const float* be1 = (const float*)d_in[7];
    const float* W2  = (const float*)d_in[8];
    // d_in[9] = b2 (cancels in BN)
    const float* g2  = (const float*)d_in[10];
    const float* be2 = (const float*)d_in[11];
    const float* fW1 = (const float*)d_in[12];
    const float* fb1 = (const float*)d_in[13];
    const float* fW2 = (const float*)d_in[14];
    const float* fb2 = (const float*)d_in[15];
    float* out = (float*)d_out;

    int E = in_sizes[1];

    k_zero<<<512, 256>>>();
    k_fill<<<(E + 255) / 256, 256>>>(src, dst, E);
    k_prep<<<(N_NODES + 255) / 256, 256>>>(x);

    // Single-wave grids: 40 regs -> 6 blocks/SM x 148 SMs = 888 blocks.
    k_aggx<<<888, 256>>>();
    k_gemm1b<<<2048, dim3(64, 4)>>>(W1);
    k_mid<<<2048, 256>>>(g1, be1);

    k_agg1<<<888, 256>>>();
    k_gemm2b<<<2048, 128>>>(W2);

    k_pool<<<1024, 128>>>(bat, g2, be2);
    k_mlp<<<N_GRAPHS, 64>>>(fW1, fb1, fW2, fb2, out);
}